// round 9
// baseline (speedup 1.0000x reference)
#include <cuda_runtime.h>
#include <cuda_bf16.h>
#include <math.h>
#include <cstdint>

// Problem dims (fixed by reference)
#define Bn  32
#define Ln  1024
#define Dn  512
#define Hn  8
#define DHn 64

#define NEGC (-4294967295.0f)   // -2^32 + 1, matches reference padding value
#define LOG2E 1.4426950408889634f

// ---------------------------------------------------------------------------
// Scratch (allocation-free rule: static __device__ globals)
// ---------------------------------------------------------------------------
__device__ float g_kmask[Bn * Ln];
__device__ float g_qmask[Bn * Ln];

#define NELEM_A ((size_t)Bn * Ln * Dn)      // 16,777,216
#define NELEM_W ((size_t)Dn * Dn)           // 262,144
__device__ __nv_bfloat16 g_qhi[NELEM_A];
__device__ __nv_bfloat16 g_qlo[NELEM_A];
__device__ __nv_bfloat16 g_khi[NELEM_A];
__device__ __nv_bfloat16 g_klo[NELEM_A];
__device__ __nv_bfloat16 g_whi[3][NELEM_W];
__device__ __nv_bfloat16 g_wlo[3][NELEM_W];

// Projected Q/K/V, bf16 hi/lo, head-major layout [b][h][l][64].
// z: 0 = Q (pre-scaled by log2e/8 for base-2 softmax), 1 = K, 2 = V
__device__ __nv_bfloat16 g_prjh[3][NELEM_A];
__device__ __nv_bfloat16 g_prjl[3][NELEM_A];

// ---------------------------------------------------------------------------
// PTX helpers (sm_80-baseline only — tcgen05 does NOT assemble at .target
// sm_103 in this harness)
// ---------------------------------------------------------------------------
__device__ __forceinline__ uint32_t smem_u32(const void* p) {
    uint32_t a;
    asm("{ .reg .u64 t; cvta.to.shared.u64 t, %1; cvt.u32.u64 %0, t; }"
        : "=r"(a) : "l"(p));
    return a;
}
__device__ __forceinline__ void cp16(uint32_t dst, const void* src) {
    asm volatile("cp.async.cg.shared.global [%0], [%1], 16;\n"
                 :: "r"(dst), "l"(src) : "memory");
}
#define CP_COMMIT() asm volatile("cp.async.commit_group;\n" ::: "memory")

__device__ __forceinline__ void ldsm_x4(uint32_t* r, uint32_t addr) {
    asm volatile("ldmatrix.sync.aligned.m8n8.x4.shared.b16 {%0,%1,%2,%3}, [%4];"
                 : "=r"(r[0]), "=r"(r[1]), "=r"(r[2]), "=r"(r[3]) : "r"(addr));
}
__device__ __forceinline__ void ldsm_x4_t(uint32_t* r, uint32_t addr) {
    asm volatile("ldmatrix.sync.aligned.m8n8.x4.trans.shared.b16 {%0,%1,%2,%3}, [%4];"
                 : "=r"(r[0]), "=r"(r[1]), "=r"(r[2]), "=r"(r[3]) : "r"(addr));
}
__device__ __forceinline__ void mma16816(float* d, const uint32_t* a, const uint32_t* b) {
    asm volatile(
        "mma.sync.aligned.m16n8k16.row.col.f32.bf16.bf16.f32 "
        "{%0,%1,%2,%3}, {%4,%5,%6,%7}, {%8,%9}, {%0,%1,%2,%3};"
        : "+f"(d[0]), "+f"(d[1]), "+f"(d[2]), "+f"(d[3])
        : "r"(a[0]), "r"(a[1]), "r"(a[2]), "r"(a[3]), "r"(b[0]), "r"(b[1]));
}
__device__ __forceinline__ uint32_t pack_bf2(float a, float b) {
    __nv_bfloat162 t = __floats2bfloat162_rn(a, b);
    return *(uint32_t*)&t;
}

// ---------------------------------------------------------------------------
// Fused conversion + padding masks. One warp per 512-elem row.
// ---------------------------------------------------------------------------
__global__ void __launch_bounds__(256) cvt_all(const float* __restrict__ q,
                                               const float* __restrict__ k,
                                               const float* __restrict__ Wq,
                                               const float* __restrict__ Wk,
                                               const float* __restrict__ Wv) {
    int w = blockIdx.x * 8 + (threadIdx.x >> 5);
    int lane = threadIdx.x & 31;
    const float* src;
    __nv_bfloat16 *hi, *lo;
    float* maskp = nullptr;
    if (w < 65536) {
        int row = w & 32767;
        size_t off = (size_t)row * Dn;
        if (w < 32768) {
            src = q + off; hi = g_qhi + off; lo = g_qlo + off;
            maskp = g_qmask + row;
        } else {
            src = k + off; hi = g_khi + off; lo = g_klo + off;
            maskp = g_kmask + row;
        }
    } else {
        int r = w - 65536;
        int z = r >> 9, row = r & 511;
        size_t off = (size_t)row * Dn;
        src = (z == 0 ? Wq : (z == 1 ? Wk : Wv)) + off;
        hi = g_whi[z] + off; lo = g_wlo[z] + off;
    }
    float s = 0.f;
#pragma unroll
    for (int i = 0; i < 4; i++) {
        int f = lane + 32 * i;
        float4 v = ((const float4*)src)[f];
        s += (v.x + v.y) + (v.z + v.w);
        __nv_bfloat162 h0 = __floats2bfloat162_rn(v.x, v.y);
        __nv_bfloat162 h1 = __floats2bfloat162_rn(v.z, v.w);
        float2 f0 = __bfloat1622float2(h0);
        float2 f1 = __bfloat1622float2(h1);
        __nv_bfloat162 l0 = __floats2bfloat162_rn(v.x - f0.x, v.y - f0.y);
        __nv_bfloat162 l1 = __floats2bfloat162_rn(v.z - f1.x, v.w - f1.y);
        ((__nv_bfloat162*)hi)[2 * f + 0] = h0;
        ((__nv_bfloat162*)hi)[2 * f + 1] = h1;
        ((__nv_bfloat162*)lo)[2 * f + 0] = l0;
        ((__nv_bfloat162*)lo)[2 * f + 1] = l1;
    }
    if (maskp) {
#pragma unroll
        for (int o = 16; o; o >>= 1) s += __shfl_xor_sync(0xffffffffu, s, o);
        if (lane == 0) *maskp = (s != 0.0f) ? 1.0f : 0.0f;
    }
}

// ---------------------------------------------------------------------------
// bf16-split GEMM (mma.sync): proj_z = A_z @ W_z^T + bias_z -> bf16 hi/lo,
// head-major [b][h][l][64]; Q pre-scaled by log2e/8.
// CTA tile 256x128, 8 warps (4 over M x 2 over N), warp tile 64x64.
// K chunks of 32, 2-stage cp.async. grid = (4, 128, 3).
// ---------------------------------------------------------------------------
#define MATA   20480                 // 256 rows * 80B
#define MATW   10240                 // 128 rows * 80B
#define STAGE_B (2 * MATA + 2 * MATW)  // 61440
#define GEMM_SMEM (2 * STAGE_B)        // 122880

__device__ __forceinline__ void load_stage(uint32_t st,
                                           const __nv_bfloat16* Ahi,
                                           const __nv_bfloat16* Alo,
                                           const __nv_bfloat16* Whi,
                                           const __nv_bfloat16* Wlo,
                                           int bm, int bn, int kc, int tid) {
    const __nv_bfloat16* as[2] = {Ahi, Alo};
#pragma unroll
    for (int a = 0; a < 2; a++) {
#pragma unroll
        for (int i = 0; i < 4; i++) {
            int idx = tid + 256 * i;            // 0..1023
            int row = idx >> 2, q4 = idx & 3;
            cp16(st + a * MATA + row * 80 + q4 * 16,
                 as[a] + (size_t)(bm + row) * Dn + kc * 32 + q4 * 8);
        }
    }
    const __nv_bfloat16* ws[2] = {Whi, Wlo};
#pragma unroll
    for (int a = 0; a < 2; a++) {
#pragma unroll
        for (int i = 0; i < 2; i++) {
            int idx = tid + 256 * i;            // 0..511
            int row = idx >> 2, q4 = idx & 3;
            cp16(st + 2 * MATA + a * MATW + row * 80 + q4 * 16,
                 ws[a] + (size_t)(bn + row) * Dn + kc * 32 + q4 * 8);
        }
    }
    CP_COMMIT();
}

__global__ void __launch_bounds__(256, 1) gemm_mma(const float* __restrict__ bq,
                                                   const float* __restrict__ bk,
                                                   const float* __restrict__ bv) {
    extern __shared__ char smem_raw[];
    uint32_t sbase = smem_u32(smem_raw);
    int tid = threadIdx.x;
    int wid = tid >> 5, lane = tid & 31;
    int wm = wid & 3;                 // 4 warps over M (64 rows each)
    int wn = wid >> 2;                // 2 warps over N (64 cols each)
    int z = blockIdx.z;
    int bn = blockIdx.x * 128;
    int bm = blockIdx.y * 256;

    const __nv_bfloat16* Ahi = (z == 0) ? g_qhi : g_khi;
    const __nv_bfloat16* Alo = (z == 0) ? g_qlo : g_klo;
    const __nv_bfloat16* Whi = g_whi[z];
    const __nv_bfloat16* Wlo = g_wlo[z];
    const float* bias = (z == 0) ? bq : (z == 1 ? bk : bv);
    float scale = (z == 0) ? (0.125f * LOG2E) : 1.0f;
    __nv_bfloat16* Ohi = g_prjh[z];
    __nv_bfloat16* Olo = g_prjl[z];

    float acc[4][8][4];
#pragma unroll
    for (int mt = 0; mt < 4; mt++)
#pragma unroll
        for (int nt = 0; nt < 8; nt++)
#pragma unroll
            for (int e = 0; e < 4; e++) acc[mt][nt][e] = 0.f;

    int a_row = lane & 15;
    int a_koff = (lane >> 4) * 16;
    int g = lane >> 3;
    int b_nadd = ((g >> 1) & 1) * 8 + (lane & 7);
    int b_kadd = (g & 1) * 8;

    load_stage(sbase, Ahi, Alo, Whi, Wlo, bm, bn, 0, tid);

#pragma unroll 1
    for (int s = 0; s < 16; s++) {
        if (s < 15) {
            load_stage(sbase + (uint32_t)((s + 1) & 1) * STAGE_B,
                       Ahi, Alo, Whi, Wlo, bm, bn, s + 1, tid);
            asm volatile("cp.async.wait_group 1;\n" ::: "memory");
        } else {
            asm volatile("cp.async.wait_group 0;\n" ::: "memory");
        }
        __syncthreads();
        uint32_t st = sbase + (uint32_t)(s & 1) * STAGE_B;

#pragma unroll
        for (int ks = 0; ks < 32; ks += 16) {
            uint32_t aH[4][4], aL[4][4], bH[8][2], bL[8][2];
#pragma unroll
            for (int mt = 0; mt < 4; mt++) {
                uint32_t ar = st + (uint32_t)((wm * 64 + mt * 16 + a_row) * 80)
                            + a_koff + ks * 2;
                ldsm_x4(aH[mt], ar);
                ldsm_x4(aL[mt], ar + MATA);
            }
#pragma unroll
            for (int ntp = 0; ntp < 4; ntp++) {
                uint32_t br = st + 2 * MATA
                            + (uint32_t)((wn * 64 + ntp * 16 + b_nadd) * 80)
                            + (ks + b_kadd) * 2;
                uint32_t t0[4], t1[4];
                ldsm_x4(t0, br);
                ldsm_x4(t1, br + MATW);
                bH[2 * ntp][0] = t0[0]; bH[2 * ntp][1] = t0[1];
                bH[2 * ntp + 1][0] = t0[2]; bH[2 * ntp + 1][1] = t0[3];
                bL[2 * ntp][0] = t1[0]; bL[2 * ntp][1] = t1[1];
                bL[2 * ntp + 1][0] = t1[2]; bL[2 * ntp + 1][1] = t1[3];
            }
#pragma unroll
            for (int mt = 0; mt < 4; mt++)
#pragma unroll
                for (int nt = 0; nt < 8; nt++) {
                    mma16816(acc[mt][nt], aH[mt], bH[nt]);
                    mma16816(acc[mt][nt], aH[mt], bL[nt]);
                    mma16816(acc[mt][nt], aL[mt], bH[nt]);
                }
        }
        __syncthreads();
    }

    // Epilogue: bias, scale, bf16 hi/lo split, head-major store
    int r = lane >> 2, c2 = (lane & 3) * 2;
#pragma unroll
    for (int mt = 0; mt < 4; mt++) {
#pragma unroll
        for (int nt = 0; nt < 8; nt++) {
            int col = bn + wn * 64 + nt * 8 + c2;
            float2 bb = *(const float2*)(bias + col);
            int hh = col >> 6, dd = col & 63;
#pragma unroll
            for (int half = 0; half < 2; half++) {
                int row = bm + wm * 64 + mt * 16 + r + half * 8;
                int bb_i = row >> 10, ll = row & 1023;
                size_t dst = ((size_t)((bb_i * Hn + hh) * Ln + ll)) * 64 + dd;
                float v0 = (acc[mt][nt][2 * half + 0] + bb.x) * scale;
                float v1 = (acc[mt][nt][2 * half + 1] + bb.y) * scale;
                __nv_bfloat162 h2 = __floats2bfloat162_rn(v0, v1);
                float2 hf = __bfloat1622float2(h2);
                __nv_bfloat162 l2 = __floats2bfloat162_rn(v0 - hf.x, v1 - hf.y);
                *(__nv_bfloat162*)(Ohi + dst) = h2;
                *(__nv_bfloat162*)(Olo + dst) = l2;
            }
        }
    }
}

// ---------------------------------------------------------------------------
// Tensor-core causal flash attention (bf16 split-3 on both matmuls)
// CTA: 128 q-rows per (b,h); 4 warps x 32 rows (2 mt frag groups);
// K tiles of 64 double-buffered; Q fragments held in REGISTERS across the
// whole kt loop (loaded once); base-2 softmax; qt descending; 2 CTAs/SM.
// ---------------------------------------------------------------------------
#define ROWB 144                       // 72 bf16 per row
#define MATB (64 * ROWB)               // 9216
#define STG  (4 * MATB)                // 36864 (Khi, Klo, Vhi, Vlo)
#define KMOFF (2 * STG)                // kmask staging (2 x 256B)
#define QOFF_H (KMOFF + 512)
#define QOFF_L (QOFF_H + 128 * ROWB)
#define ATTN_SMEM (QOFF_L + 128 * ROWB)   // 111104

__global__ void __launch_bounds__(128, 2) attn_mma(const float* __restrict__ queries,
                                                   float* __restrict__ out) {
    extern __shared__ char smraw[];
    uint32_t sb = smem_u32(smraw);
    int tid = threadIdx.x, wid = tid >> 5, lane = tid & 31;
    int qt = (int)gridDim.x - 1 - (int)blockIdx.x;   // heavy tiles first
    int h = blockIdx.y, b = blockIdx.z;
    int bh = b * Hn + h;
    int wq0 = wid * 32;

    const __nv_bfloat16* Qh = g_prjh[0] + (size_t)bh * Ln * 64;
    const __nv_bfloat16* Ql = g_prjl[0] + (size_t)bh * Ln * 64;
    const __nv_bfloat16* Kh = g_prjh[1] + (size_t)bh * Ln * 64;
    const __nv_bfloat16* Kl = g_prjl[1] + (size_t)bh * Ln * 64;
    const __nv_bfloat16* Vh = g_prjh[2] + (size_t)bh * Ln * 64;
    const __nv_bfloat16* Vl = g_prjl[2] + (size_t)bh * Ln * 64;

    // ---- stage Q tile into SMEM (commit group 0) ----
#pragma unroll
    for (int i = 0; i < 8; i++) {
        int idx = tid + 128 * i;          // 0..1023
        int row = idx >> 3, ch = idx & 7;
        cp16(sb + QOFF_H + row * ROWB + ch * 16,
             Qh + (size_t)(qt * 128 + row) * 64 + ch * 8);
        cp16(sb + QOFF_L + row * ROWB + ch * 16,
             Ql + (size_t)(qt * 128 + row) * 64 + ch * 8);
    }
    CP_COMMIT();

    auto load_kv = [&](int kt2) {
        uint32_t st = sb + (uint32_t)(kt2 & 1) * STG;
        int kg0 = kt2 * 64;
        const __nv_bfloat16* srcs[4] = {Kh, Kl, Vh, Vl};
#pragma unroll
        for (int m = 0; m < 4; m++) {
#pragma unroll
            for (int i = 0; i < 4; i++) {
                int idx = tid + 128 * i;   // 0..511
                int row = idx >> 3, ch = idx & 7;
                cp16(st + m * MATB + row * ROWB + ch * 16,
                     srcs[m] + (size_t)(kg0 + row) * 64 + ch * 8);
            }
        }
        if (tid < 16)
            cp16(sb + KMOFF + (uint32_t)(kt2 & 1) * 256 + tid * 16,
                 g_kmask + b * Ln + kg0 + tid * 4);
        CP_COMMIT();
    };

    load_kv(0);   // commit group 1 (in flight while we consume Q)

    // ---- wait for Q only, then load Q fragments into registers (held) ----
    asm volatile("cp.async.wait_group 1;\n" ::: "memory");
    __syncthreads();
    uint32_t qfh[4][2][4], qfl[4][2][4];
#pragma unroll
    for (int dk = 0; dk < 4; dk++)
#pragma unroll
        for (int mt = 0; mt < 2; mt++) {
            uint32_t ar = sb + QOFF_H
                + (uint32_t)((wq0 + mt * 16 + (lane & 15)) * ROWB)
                + (uint32_t)((dk * 16 + (lane >> 4) * 8) * 2);
            ldsm_x4(qfh[dk][mt], ar);
            ldsm_x4(qfl[dk][mt], ar + (QOFF_L - QOFF_H));
        }

    float o[2][8][4];
#pragma unroll
    for (int mt = 0; mt < 2; mt++)
#pragma unroll
        for (int nt = 0; nt < 8; nt++)
#pragma unroll
            for (int e = 0; e < 4; e++) o[mt][nt][e] = 0.f;
    float mrow[2][2], lsum[2][2];
#pragma unroll
    for (int mt = 0; mt < 2; mt++) {
        mrow[mt][0] = -INFINITY; mrow[mt][1] = -INFINITY;
        lsum[mt][0] = 0.f;       lsum[mt][1] = 0.f;
    }

    int ntk = 2 * qt + 2;
    int c2 = (lane & 3) * 2, rr = lane >> 2;
    int rowq[2][2];
#pragma unroll
    for (int mt = 0; mt < 2; mt++) {
        rowq[mt][0] = qt * 128 + wq0 + mt * 16 + rr;
        rowq[mt][1] = rowq[mt][0] + 8;
    }

#pragma unroll 1
    for (int kt = 0; kt < ntk; kt++) {
        if (kt + 1 < ntk) {
            load_kv(kt + 1);
            asm volatile("cp.async.wait_group 1;\n" ::: "memory");
        } else {
            asm volatile("cp.async.wait_group 0;\n" ::: "memory");
        }
        __syncthreads();
        uint32_t st = sb + (uint32_t)(kt & 1) * STG;

        // ---- S = Q K^T  (base-2 domain: Q pre-scaled by log2e/8) ----
        float s[2][8][4];
#pragma unroll
        for (int mt = 0; mt < 2; mt++)
#pragma unroll
            for (int nt = 0; nt < 8; nt++)
#pragma unroll
                for (int e = 0; e < 4; e++) s[mt][nt][e] = 0.f;

#pragma unroll
        for (int dk = 0; dk < 4; dk++) {
#pragma unroll
            for (int ntp = 0; ntp < 4; ntp++) {
                uint32_t br = st
                    + (uint32_t)((ntp * 16 + (lane & 7) + ((lane >> 4) & 1) * 8) * ROWB)
                    + (uint32_t)((dk * 16 + ((lane >> 3) & 1) * 8) * 2);
                uint32_t th[4], tl[4];
                ldsm_x4(th, br);
                ldsm_x4(tl, br + MATB);
#pragma unroll
                for (int mt = 0; mt < 2; mt++) {
                    mma16816(s[mt][2 * ntp],     qfh[dk][mt], &th[0]);
                    mma16816(s[mt][2 * ntp],     qfh[dk][mt], &tl[0]);
                    mma16816(s[mt][2 * ntp],     qfl[dk][mt], &th[0]);
                    mma16816(s[mt][2 * ntp + 1], qfh[dk][mt], &th[2]);
                    mma16816(s[mt][2 * ntp + 1], qfh[dk][mt], &tl[2]);
                    mma16816(s[mt][2 * ntp + 1], qfl[dk][mt], &th[2]);
                }
            }
        }

        // ---- masks ----
        const float* kmp = (const float*)(smraw + KMOFF + (kt & 1) * 256);
        int kbase = kt * 64;
#pragma unroll
        for (int nt = 0; nt < 8; nt++) {
            int col = kbase + nt * 8 + c2;
            float km0 = kmp[nt * 8 + c2];
            float km1 = kmp[nt * 8 + c2 + 1];
#pragma unroll
            for (int mt = 0; mt < 2; mt++) {
                if (km0 == 0.f || col > rowq[mt][0])     s[mt][nt][0] = NEGC;
                if (km1 == 0.f || col + 1 > rowq[mt][0]) s[mt][nt][1] = NEGC;
                if (km0 == 0.f || col > rowq[mt][1])     s[mt][nt][2] = NEGC;
                if (km1 == 0.f || col + 1 > rowq[mt][1]) s[mt][nt][3] = NEGC;
            }
        }

        // ---- online softmax (base-2) ----
#pragma unroll
        for (int mt = 0; mt < 2; mt++) {
            float mx0 = -INFINITY, mx1 = -INFINITY;
#pragma unroll
            for (int nt = 0; nt < 8; nt++) {
                mx0 = fmaxf(mx0, fmaxf(s[mt][nt][0], s[mt][nt][1]));
                mx1 = fmaxf(mx1, fmaxf(s[mt][nt][2], s[mt][nt][3]));
            }
            mx0 = fmaxf(mx0, __shfl_xor_sync(0xffffffffu, mx0, 1));
            mx0 = fmaxf(mx0, __shfl_xor_sync(0xffffffffu, mx0, 2));
            mx1 = fmaxf(mx1, __shfl_xor_sync(0xffffffffu, mx1, 1));
            mx1 = fmaxf(mx1, __shfl_xor_sync(0xffffffffu, mx1, 2));
            float mn0 = fmaxf(mrow[mt][0], mx0), mn1 = fmaxf(mrow[mt][1], mx1);
            float corr0 = exp2f(mrow[mt][0] - mn0), corr1 = exp2f(mrow[mt][1] - mn1);
            mrow[mt][0] = mn0; mrow[mt][1] = mn1;

            float ps0 = 0.f, ps1 = 0.f;
#pragma unroll
            for (int nt = 0; nt < 8; nt++) {
                s[mt][nt][0] = exp2f(s[mt][nt][0] - mn0);
                s[mt][nt][1] = exp2f(s[mt][nt][1] - mn0);
                s[mt][nt][2] = exp2f(s[mt][nt][2] - mn1);
                s[mt][nt][3] = exp2f(s[mt][nt][3] - mn1);
                ps0 += s[mt][nt][0] + s[mt][nt][1];
                ps1 += s[mt][nt][2] + s[mt][nt][3];
            }
            ps0 += __shfl_xor_sync(0xffffffffu, ps0, 1);
            ps0 += __shfl_xor_sync(0xffffffffu, ps0, 2);
            ps1 += __shfl_xor_sync(0xffffffffu, ps1, 1);
            ps1 += __shfl_xor_sync(0xffffffffu, ps1, 2);
            lsum[mt][0] = lsum[mt][0] * corr0 + ps0;
            lsum[mt][1] = lsum[mt][1] * corr1 + ps1;
#pragma unroll
            for (int nt = 0; nt < 8; nt++) {
                o[mt][nt][0] *= corr0; o[mt][nt][1] *= corr0;
                o[mt][nt][2] *= corr1; o[mt][nt][3] *= corr1;
            }
        }

        // ---- O += P V  (C-frag order == A-frag order; V via ldsm.trans) ----
#pragma unroll
        for (int ks = 0; ks < 4; ks++) {
            uint32_t aH[2][4], aL[2][4];
#pragma unroll
            for (int mt = 0; mt < 2; mt++) {
#pragma unroll
                for (int half = 0; half < 2; half++) {
                    int nt = 2 * ks + half;
                    float p0 = s[mt][nt][0], p1 = s[mt][nt][1];
                    float p2 = s[mt][nt][2], p3 = s[mt][nt][3];
                    __nv_bfloat162 h01 = __floats2bfloat162_rn(p0, p1);
                    __nv_bfloat162 h23 = __floats2bfloat162_rn(p2, p3);
                    float2 f01 = __bfloat1622float2(h01);
                    float2 f23 = __bfloat1622float2(h23);
                    aH[mt][2 * half + 0] = *(uint32_t*)&h01;
                    aH[mt][2 * half + 1] = *(uint32_t*)&h23;
                    aL[mt][2 * half + 0] = pack_bf2(p0 - f01.x, p1 - f01.y);
                    aL[mt][2 * half + 1] = pack_bf2(p2 - f23.x, p3 - f23.y);
                }
            }
#pragma unroll
            for (int ntp = 0; ntp < 4; ntp++) {
                uint32_t br = st + 2 * MATB
                    + (uint32_t)((ks * 16 + (lane & 7) + ((lane >> 3) & 1) * 8) * ROWB)
                    + (uint32_t)((ntp * 16 + ((lane >> 4) & 1) * 8) * 2);
                uint32_t vh[4], vl[4];
                ldsm_x4_t(vh, br);
                ldsm_x4_t(vl, br + MATB);
#pragma unroll
                for (int mt = 0; mt < 2; mt++) {
                    mma16816(o[mt][2 * ntp],     aH[mt], &vh[0]);
                    mma16816(o[mt][2 * ntp],     aH[mt], &vl[0]);
                    mma16816(o[mt][2 * ntp],     aL[mt], &vh[0]);
                    mma16816(o[mt][2 * ntp + 1], aH[mt], &vh[2]);
                    mma16816(o[mt][2 * ntp + 1], aH[mt], &vl[2]);
                    mma16816(o[mt][2 * ntp + 1], aL[mt], &vh[2]);
                }
            }
        }
        __syncthreads();
    }

    // ---- epilogue: normalize, query mask, residual, fp32 store ----
#pragma unroll
    for (int mt = 0; mt < 2; mt++) {
        float qm0 = g_qmask[b * Ln + rowq[mt][0]];
        float qm1 = g_qmask[b * Ln + rowq[mt][1]];
        float f0 = qm0 / lsum[mt][0], f1 = qm1 / lsum[mt][1];
        size_t base0 = ((size_t)(b * Ln + rowq[mt][0])) * Dn + h * 64;
        size_t base1 = ((size_t)(b * Ln + rowq[mt][1])) * Dn + h * 64;
#pragma unroll
        for (int nt = 0; nt < 8; nt++) {
            int d = nt * 8 + c2;
            float2 r0v = *(const float2*)(queries + base0 + d);
            float2 r1v = *(const float2*)(queries + base1 + d);
            float2 o0, o1;
            o0.x = o[mt][nt][0] * f0 + r0v.x; o0.y = o[mt][nt][1] * f0 + r0v.y;
            o1.x = o[mt][nt][2] * f1 + r1v.x; o1.y = o[mt][nt][3] * f1 + r1v.y;
            *(float2*)(out + base0 + d) = o0;
            *(float2*)(out + base1 + d) = o1;
        }
    }
}

// ---------------------------------------------------------------------------
extern "C" void kernel_launch(void* const* d_in, const int* in_sizes, int n_in,
                              void* d_out, int out_size) {
    (void)in_sizes; (void)n_in; (void)out_size;
    const float* queries = (const float*)d_in[0];
    const float* keys    = (const float*)d_in[1];
    const float* Wq = (const float*)d_in[2];
    const float* bq = (const float*)d_in[3];
    const float* Wk = (const float*)d_in[4];
    const float* bk = (const float*)d_in[5];
    const float* Wv = (const float*)d_in[6];
    const float* bv = (const float*)d_in[7];
    float* out = (float*)d_out;

    cudaFuncSetAttribute(gemm_mma,
                         cudaFuncAttributeMaxDynamicSharedMemorySize, GEMM_SMEM);
    cudaFuncSetAttribute(attn_mma,
                         cudaFuncAttributeMaxDynamicSharedMemorySize, ATTN_SMEM);

    // 1) fused bf16 hi/lo splits + padding masks
    cvt_all<<<8384, 256>>>(queries, keys, Wq, Wk, Wv);

    // 2) QKV projections (tensor cores), bf16 hi/lo head-major outputs
    gemm_mma<<<dim3(4, 128, 3), 256, GEMM_SMEM>>>(bq, bk, bv);

    // 3) tensor-core attention + residual (Q fragments register-resident)
    attn_mma<<<dim3(8, 8, 32), 128, ATTN_SMEM>>>(queries, out);
}

// round 10
// speedup vs baseline: 1.1191x; 1.1191x over previous
#include <cuda_runtime.h>
#include <cuda_fp16.h>
#include <math.h>
#include <cstdint>

// Problem dims (fixed by reference)
#define Bn  32
#define Ln  1024
#define Dn  512
#define Hn  8
#define DHn 64

#define NEGC (-4294967295.0f)   // -2^32 + 1, matches reference padding value
#define LOG2E 1.4426950408889634f

// ---------------------------------------------------------------------------
// Scratch (allocation-free rule: static __device__ globals)
// ---------------------------------------------------------------------------
__device__ float g_kmask[Bn * Ln];
__device__ float g_qmask[Bn * Ln];

#define NELEM_A ((size_t)Bn * Ln * Dn)      // 16,777,216
#define NELEM_W ((size_t)Dn * Dn)           // 262,144
__device__ __half g_qhi[NELEM_A];
__device__ __half g_qlo[NELEM_A];
__device__ __half g_khi[NELEM_A];
__device__ __half g_klo[NELEM_A];
__device__ __half g_whi[3][NELEM_W];
__device__ __half g_wlo[3][NELEM_W];

// Projected Q/K/V, fp16 hi/lo, head-major layout [b][h][l][64].
// z: 0 = Q (pre-scaled by log2e/8 for base-2 softmax), 1 = K, 2 = V
__device__ __half g_prjh[3][NELEM_A];
__device__ __half g_prjl[3][NELEM_A];

// ---------------------------------------------------------------------------
// PTX helpers (sm_80-baseline only — tcgen05 does NOT assemble at .target
// sm_103 in this harness)
// ---------------------------------------------------------------------------
__device__ __forceinline__ uint32_t smem_u32(const void* p) {
    uint32_t a;
    asm("{ .reg .u64 t; cvta.to.shared.u64 t, %1; cvt.u32.u64 %0, t; }"
        : "=r"(a) : "l"(p));
    return a;
}
__device__ __forceinline__ void cp16(uint32_t dst, const void* src) {
    asm volatile("cp.async.cg.shared.global [%0], [%1], 16;\n"
                 :: "r"(dst), "l"(src) : "memory");
}
#define CP_COMMIT() asm volatile("cp.async.commit_group;\n" ::: "memory")

__device__ __forceinline__ void ldsm_x4(uint32_t* r, uint32_t addr) {
    asm volatile("ldmatrix.sync.aligned.m8n8.x4.shared.b16 {%0,%1,%2,%3}, [%4];"
                 : "=r"(r[0]), "=r"(r[1]), "=r"(r[2]), "=r"(r[3]) : "r"(addr));
}
__device__ __forceinline__ void ldsm_x4_t(uint32_t* r, uint32_t addr) {
    asm volatile("ldmatrix.sync.aligned.m8n8.x4.trans.shared.b16 {%0,%1,%2,%3}, [%4];"
                 : "=r"(r[0]), "=r"(r[1]), "=r"(r[2]), "=r"(r[3]) : "r"(addr));
}
__device__ __forceinline__ void mma16816(float* d, const uint32_t* a, const uint32_t* b) {
    asm volatile(
        "mma.sync.aligned.m16n8k16.row.col.f32.f16.f16.f32 "
        "{%0,%1,%2,%3}, {%4,%5,%6,%7}, {%8,%9}, {%0,%1,%2,%3};"
        : "+f"(d[0]), "+f"(d[1]), "+f"(d[2]), "+f"(d[3])
        : "r"(a[0]), "r"(a[1]), "r"(a[2]), "r"(a[3]), "r"(b[0]), "r"(b[1]));
}
__device__ __forceinline__ uint32_t pack_h2(float a, float b) {
    __half2 t = __floats2half2_rn(a, b);
    return *(uint32_t*)&t;
}

// ---------------------------------------------------------------------------
// Fused conversion + padding masks. One warp per 512-elem row.
// ---------------------------------------------------------------------------
__global__ void __launch_bounds__(256) cvt_all(const float* __restrict__ q,
                                               const float* __restrict__ k,
                                               const float* __restrict__ Wq,
                                               const float* __restrict__ Wk,
                                               const float* __restrict__ Wv) {
    int w = blockIdx.x * 8 + (threadIdx.x >> 5);
    int lane = threadIdx.x & 31;
    const float* src;
    __half *hi, *lo;
    float* maskp = nullptr;
    if (w < 65536) {
        int row = w & 32767;
        size_t off = (size_t)row * Dn;
        if (w < 32768) {
            src = q + off; hi = g_qhi + off; lo = g_qlo + off;
            maskp = g_qmask + row;
        } else {
            src = k + off; hi = g_khi + off; lo = g_klo + off;
            maskp = g_kmask + row;
        }
    } else {
        int r = w - 65536;
        int z = r >> 9, row = r & 511;
        size_t off = (size_t)row * Dn;
        src = (z == 0 ? Wq : (z == 1 ? Wk : Wv)) + off;
        hi = g_whi[z] + off; lo = g_wlo[z] + off;
    }
    float s = 0.f;
#pragma unroll
    for (int i = 0; i < 4; i++) {
        int f = lane + 32 * i;
        float4 v = ((const float4*)src)[f];
        s += (v.x + v.y) + (v.z + v.w);
        __half2 h0 = __floats2half2_rn(v.x, v.y);
        __half2 h1 = __floats2half2_rn(v.z, v.w);
        float2 f0 = __half22float2(h0);
        float2 f1 = __half22float2(h1);
        __half2 l0 = __floats2half2_rn(v.x - f0.x, v.y - f0.y);
        __half2 l1 = __floats2half2_rn(v.z - f1.x, v.w - f1.y);
        ((__half2*)hi)[2 * f + 0] = h0;
        ((__half2*)hi)[2 * f + 1] = h1;
        ((__half2*)lo)[2 * f + 0] = l0;
        ((__half2*)lo)[2 * f + 1] = l1;
    }
    if (maskp) {
#pragma unroll
        for (int o = 16; o; o >>= 1) s += __shfl_xor_sync(0xffffffffu, s, o);
        if (lane == 0) *maskp = (s != 0.0f) ? 1.0f : 0.0f;
    }
}

// ---------------------------------------------------------------------------
// fp16-split GEMM (mma.sync): proj_z = A_z @ W_z^T + bias_z -> fp16 hi/lo,
// head-major [b][h][l][64]; Q pre-scaled by log2e/8.
// CTA tile 256x128, 8 warps (4 over M x 2 over N), warp tile 64x64.
// K chunks of 32, 2-stage cp.async. grid = (4, 128, 3).
// ---------------------------------------------------------------------------
#define MATA   20480                 // 256 rows * 80B
#define MATW   10240                 // 128 rows * 80B
#define STAGE_B (2 * MATA + 2 * MATW)  // 61440
#define GEMM_SMEM (2 * STAGE_B)        // 122880

__device__ __forceinline__ void load_stage(uint32_t st,
                                           const __half* Ahi,
                                           const __half* Alo,
                                           const __half* Whi,
                                           const __half* Wlo,
                                           int bm, int bn, int kc, int tid) {
    const __half* as[2] = {Ahi, Alo};
#pragma unroll
    for (int a = 0; a < 2; a++) {
#pragma unroll
        for (int i = 0; i < 4; i++) {
            int idx = tid + 256 * i;            // 0..1023
            int row = idx >> 2, q4 = idx & 3;
            cp16(st + a * MATA + row * 80 + q4 * 16,
                 as[a] + (size_t)(bm + row) * Dn + kc * 32 + q4 * 8);
        }
    }
    const __half* ws[2] = {Whi, Wlo};
#pragma unroll
    for (int a = 0; a < 2; a++) {
#pragma unroll
        for (int i = 0; i < 2; i++) {
            int idx = tid + 256 * i;            // 0..511
            int row = idx >> 2, q4 = idx & 3;
            cp16(st + 2 * MATA + a * MATW + row * 80 + q4 * 16,
                 ws[a] + (size_t)(bn + row) * Dn + kc * 32 + q4 * 8);
        }
    }
    CP_COMMIT();
}

__global__ void __launch_bounds__(256, 1) gemm_mma(const float* __restrict__ bq,
                                                   const float* __restrict__ bk,
                                                   const float* __restrict__ bv) {
    extern __shared__ char smem_raw[];
    uint32_t sbase = smem_u32(smem_raw);
    int tid = threadIdx.x;
    int wid = tid >> 5, lane = tid & 31;
    int wm = wid & 3;                 // 4 warps over M (64 rows each)
    int wn = wid >> 2;                // 2 warps over N (64 cols each)
    int z = blockIdx.z;
    int bn = blockIdx.x * 128;
    int bm = blockIdx.y * 256;

    const __half* Ahi = (z == 0) ? g_qhi : g_khi;
    const __half* Alo = (z == 0) ? g_qlo : g_klo;
    const __half* Whi = g_whi[z];
    const __half* Wlo = g_wlo[z];
    const float* bias = (z == 0) ? bq : (z == 1 ? bk : bv);
    float scale = (z == 0) ? (0.125f * LOG2E) : 1.0f;
    __half* Ohi = g_prjh[z];
    __half* Olo = g_prjl[z];

    float acc[4][8][4];
#pragma unroll
    for (int mt = 0; mt < 4; mt++)
#pragma unroll
        for (int nt = 0; nt < 8; nt++)
#pragma unroll
            for (int e = 0; e < 4; e++) acc[mt][nt][e] = 0.f;

    int a_row = lane & 15;
    int a_koff = (lane >> 4) * 16;
    int g = lane >> 3;
    int b_nadd = ((g >> 1) & 1) * 8 + (lane & 7);
    int b_kadd = (g & 1) * 8;

    load_stage(sbase, Ahi, Alo, Whi, Wlo, bm, bn, 0, tid);

#pragma unroll 1
    for (int s = 0; s < 16; s++) {
        if (s < 15) {
            load_stage(sbase + (uint32_t)((s + 1) & 1) * STAGE_B,
                       Ahi, Alo, Whi, Wlo, bm, bn, s + 1, tid);
            asm volatile("cp.async.wait_group 1;\n" ::: "memory");
        } else {
            asm volatile("cp.async.wait_group 0;\n" ::: "memory");
        }
        __syncthreads();
        uint32_t st = sbase + (uint32_t)(s & 1) * STAGE_B;

#pragma unroll
        for (int ks = 0; ks < 32; ks += 16) {
            uint32_t aH[4][4], aL[4][4], bH[8][2], bL[8][2];
#pragma unroll
            for (int mt = 0; mt < 4; mt++) {
                uint32_t ar = st + (uint32_t)((wm * 64 + mt * 16 + a_row) * 80)
                            + a_koff + ks * 2;
                ldsm_x4(aH[mt], ar);
                ldsm_x4(aL[mt], ar + MATA);
            }
#pragma unroll
            for (int ntp = 0; ntp < 4; ntp++) {
                uint32_t br = st + 2 * MATA
                            + (uint32_t)((wn * 64 + ntp * 16 + b_nadd) * 80)
                            + (ks + b_kadd) * 2;
                uint32_t t0[4], t1[4];
                ldsm_x4(t0, br);
                ldsm_x4(t1, br + MATW);
                bH[2 * ntp][0] = t0[0]; bH[2 * ntp][1] = t0[1];
                bH[2 * ntp + 1][0] = t0[2]; bH[2 * ntp + 1][1] = t0[3];
                bL[2 * ntp][0] = t1[0]; bL[2 * ntp][1] = t1[1];
                bL[2 * ntp + 1][0] = t1[2]; bL[2 * ntp + 1][1] = t1[3];
            }
#pragma unroll
            for (int mt = 0; mt < 4; mt++)
#pragma unroll
                for (int nt = 0; nt < 8; nt++) {
                    mma16816(acc[mt][nt], aH[mt], bH[nt]);
                    mma16816(acc[mt][nt], aH[mt], bL[nt]);
                    mma16816(acc[mt][nt], aL[mt], bH[nt]);
                }
        }
        __syncthreads();
    }

    // Epilogue: bias, scale, fp16 hi/lo split, head-major store
    int r = lane >> 2, c2 = (lane & 3) * 2;
#pragma unroll
    for (int mt = 0; mt < 4; mt++) {
#pragma unroll
        for (int nt = 0; nt < 8; nt++) {
            int col = bn + wn * 64 + nt * 8 + c2;
            float2 bb = *(const float2*)(bias + col);
            int hh = col >> 6, dd = col & 63;
#pragma unroll
            for (int half = 0; half < 2; half++) {
                int row = bm + wm * 64 + mt * 16 + r + half * 8;
                int bb_i = row >> 10, ll = row & 1023;
                size_t dst = ((size_t)((bb_i * Hn + hh) * Ln + ll)) * 64 + dd;
                float v0 = (acc[mt][nt][2 * half + 0] + bb.x) * scale;
                float v1 = (acc[mt][nt][2 * half + 1] + bb.y) * scale;
                __half2 h2v = __floats2half2_rn(v0, v1);
                float2 hf = __half22float2(h2v);
                __half2 l2v = __floats2half2_rn(v0 - hf.x, v1 - hf.y);
                *(__half2*)(Ohi + dst) = h2v;
                *(__half2*)(Olo + dst) = l2v;
            }
        }
    }
}

// ---------------------------------------------------------------------------
// Tensor-core causal flash attention.
// S = QK^T: fp16 split-3 (accuracy for logits). O += PV: single fp16 MMA
// (P_hi x V_hi) — fp16's 2^-11 rounding keeps the dropped terms ~7e-4 of |O|.
// CTA: 128 q-rows per (b,h); 4 warps x 32 rows; K tiles of 64 double-buffered
// (Khi, Klo, Vhi only — V_lo eliminated); base-2 softmax; qt descending;
// 2 CTAs/SM.
// ---------------------------------------------------------------------------
#define ROWB 144                       // 72 fp16 per row
#define MATB (64 * ROWB)               // 9216
#define STG  (3 * MATB)                // 27648 (Khi, Klo, Vhi)
#define KMOFF (2 * STG)                // 55296: kmask staging (2 x 256B)
#define QOFF_H (KMOFF + 512)           // 55808
#define QOFF_L (QOFF_H + 128 * ROWB)   // 74240
#define ATTN_SMEM (QOFF_L + 128 * ROWB)   // 92672

__global__ void __launch_bounds__(128, 2) attn_mma(const float* __restrict__ queries,
                                                   float* __restrict__ out) {
    extern __shared__ char smraw[];
    uint32_t sb = smem_u32(smraw);
    int tid = threadIdx.x, wid = tid >> 5, lane = tid & 31;
    int qt = (int)gridDim.x - 1 - (int)blockIdx.x;   // heavy tiles first
    int h = blockIdx.y, b = blockIdx.z;
    int bh = b * Hn + h;
    int wq0 = wid * 32;

    const __half* Qh = g_prjh[0] + (size_t)bh * Ln * 64;
    const __half* Ql = g_prjl[0] + (size_t)bh * Ln * 64;
    const __half* Kh = g_prjh[1] + (size_t)bh * Ln * 64;
    const __half* Kl = g_prjl[1] + (size_t)bh * Ln * 64;
    const __half* Vh = g_prjh[2] + (size_t)bh * Ln * 64;

    // ---- Q tile into dedicated SMEM ----
#pragma unroll
    for (int i = 0; i < 8; i++) {
        int idx = tid + 128 * i;          // 0..1023
        int row = idx >> 3, ch = idx & 7;
        cp16(sb + QOFF_H + row * ROWB + ch * 16,
             Qh + (size_t)(qt * 128 + row) * 64 + ch * 8);
        cp16(sb + QOFF_L + row * ROWB + ch * 16,
             Ql + (size_t)(qt * 128 + row) * 64 + ch * 8);
    }
    CP_COMMIT();

    float o[2][8][4];
#pragma unroll
    for (int mt = 0; mt < 2; mt++)
#pragma unroll
        for (int nt = 0; nt < 8; nt++)
#pragma unroll
            for (int e = 0; e < 4; e++) o[mt][nt][e] = 0.f;
    float mrow[2][2], lsum[2][2];
#pragma unroll
    for (int mt = 0; mt < 2; mt++) {
        mrow[mt][0] = -INFINITY; mrow[mt][1] = -INFINITY;
        lsum[mt][0] = 0.f;       lsum[mt][1] = 0.f;
    }

    int ntk = 2 * qt + 2;

    auto load_kv = [&](int kt2) {
        uint32_t st = sb + (uint32_t)(kt2 & 1) * STG;
        int kg0 = kt2 * 64;
        const __half* srcs[3] = {Kh, Kl, Vh};
#pragma unroll
        for (int m = 0; m < 3; m++) {
#pragma unroll
            for (int i = 0; i < 4; i++) {
                int idx = tid + 128 * i;   // 0..511
                int row = idx >> 3, ch = idx & 7;
                cp16(st + m * MATB + row * ROWB + ch * 16,
                     srcs[m] + (size_t)(kg0 + row) * 64 + ch * 8);
            }
        }
        if (tid < 16)
            cp16(sb + KMOFF + (uint32_t)(kt2 & 1) * 256 + tid * 16,
                 g_kmask + b * Ln + kg0 + tid * 4);
        CP_COMMIT();
    };

    load_kv(0);

    int c2 = (lane & 3) * 2, rr = lane >> 2;
    int rowq[2][2];
#pragma unroll
    for (int mt = 0; mt < 2; mt++) {
        rowq[mt][0] = qt * 128 + wq0 + mt * 16 + rr;
        rowq[mt][1] = rowq[mt][0] + 8;
    }

#pragma unroll 1
    for (int kt = 0; kt < ntk; kt++) {
        if (kt + 1 < ntk) {
            load_kv(kt + 1);
            asm volatile("cp.async.wait_group 1;\n" ::: "memory");
        } else {
            asm volatile("cp.async.wait_group 0;\n" ::: "memory");
        }
        __syncthreads();
        uint32_t st = sb + (uint32_t)(kt & 1) * STG;

        // ---- S = Q K^T  (fp16 split-3; base-2 domain) ----
        float s[2][8][4];
#pragma unroll
        for (int mt = 0; mt < 2; mt++)
#pragma unroll
            for (int nt = 0; nt < 8; nt++)
#pragma unroll
                for (int e = 0; e < 4; e++) s[mt][nt][e] = 0.f;

#pragma unroll
        for (int dk = 0; dk < 4; dk++) {
            uint32_t qfh[2][4], qfl[2][4];
#pragma unroll
            for (int mt = 0; mt < 2; mt++) {
                uint32_t ar = sb + QOFF_H
                    + (uint32_t)((wq0 + mt * 16 + (lane & 15)) * ROWB)
                    + (uint32_t)((dk * 16 + (lane >> 4) * 8) * 2);
                ldsm_x4(qfh[mt], ar);
                ldsm_x4(qfl[mt], ar + (QOFF_L - QOFF_H));
            }
#pragma unroll
            for (int ntp = 0; ntp < 4; ntp++) {
                uint32_t br = st
                    + (uint32_t)((ntp * 16 + (lane & 7) + ((lane >> 4) & 1) * 8) * ROWB)
                    + (uint32_t)((dk * 16 + ((lane >> 3) & 1) * 8) * 2);
                uint32_t th[4], tl[4];
                ldsm_x4(th, br);
                ldsm_x4(tl, br + MATB);
#pragma unroll
                for (int mt = 0; mt < 2; mt++) {
                    mma16816(s[mt][2 * ntp],     qfh[mt], &th[0]);
                    mma16816(s[mt][2 * ntp],     qfh[mt], &tl[0]);
                    mma16816(s[mt][2 * ntp],     qfl[mt], &th[0]);
                    mma16816(s[mt][2 * ntp + 1], qfh[mt], &th[2]);
                    mma16816(s[mt][2 * ntp + 1], qfh[mt], &tl[2]);
                    mma16816(s[mt][2 * ntp + 1], qfl[mt], &th[2]);
                }
            }
        }

        // ---- masks ----
        const float* kmp = (const float*)(smraw + KMOFF + (kt & 1) * 256);
        int kbase = kt * 64;
#pragma unroll
        for (int nt = 0; nt < 8; nt++) {
            int col = kbase + nt * 8 + c2;
            float km0 = kmp[nt * 8 + c2];
            float km1 = kmp[nt * 8 + c2 + 1];
#pragma unroll
            for (int mt = 0; mt < 2; mt++) {
                if (km0 == 0.f || col > rowq[mt][0])     s[mt][nt][0] = NEGC;
                if (km1 == 0.f || col + 1 > rowq[mt][0]) s[mt][nt][1] = NEGC;
                if (km0 == 0.f || col > rowq[mt][1])     s[mt][nt][2] = NEGC;
                if (km1 == 0.f || col + 1 > rowq[mt][1]) s[mt][nt][3] = NEGC;
            }
        }

        // ---- online softmax (base-2) ----
#pragma unroll
        for (int mt = 0; mt < 2; mt++) {
            float mx0 = -INFINITY, mx1 = -INFINITY;
#pragma unroll
            for (int nt = 0; nt < 8; nt++) {
                mx0 = fmaxf(mx0, fmaxf(s[mt][nt][0], s[mt][nt][1]));
                mx1 = fmaxf(mx1, fmaxf(s[mt][nt][2], s[mt][nt][3]));
            }
            mx0 = fmaxf(mx0, __shfl_xor_sync(0xffffffffu, mx0, 1));
            mx0 = fmaxf(mx0, __shfl_xor_sync(0xffffffffu, mx0, 2));
            mx1 = fmaxf(mx1, __shfl_xor_sync(0xffffffffu, mx1, 1));
            mx1 = fmaxf(mx1, __shfl_xor_sync(0xffffffffu, mx1, 2));
            float mn0 = fmaxf(mrow[mt][0], mx0), mn1 = fmaxf(mrow[mt][1], mx1);
            float corr0 = exp2f(mrow[mt][0] - mn0), corr1 = exp2f(mrow[mt][1] - mn1);
            mrow[mt][0] = mn0; mrow[mt][1] = mn1;

            float ps0 = 0.f, ps1 = 0.f;
#pragma unroll
            for (int nt = 0; nt < 8; nt++) {
                s[mt][nt][0] = exp2f(s[mt][nt][0] - mn0);
                s[mt][nt][1] = exp2f(s[mt][nt][1] - mn0);
                s[mt][nt][2] = exp2f(s[mt][nt][2] - mn1);
                s[mt][nt][3] = exp2f(s[mt][nt][3] - mn1);
                ps0 += s[mt][nt][0] + s[mt][nt][1];
                ps1 += s[mt][nt][2] + s[mt][nt][3];
            }
            ps0 += __shfl_xor_sync(0xffffffffu, ps0, 1);
            ps0 += __shfl_xor_sync(0xffffffffu, ps0, 2);
            ps1 += __shfl_xor_sync(0xffffffffu, ps1, 1);
            ps1 += __shfl_xor_sync(0xffffffffu, ps1, 2);
            lsum[mt][0] = lsum[mt][0] * corr0 + ps0;
            lsum[mt][1] = lsum[mt][1] * corr1 + ps1;
#pragma unroll
            for (int nt = 0; nt < 8; nt++) {
                o[mt][nt][0] *= corr0; o[mt][nt][1] *= corr0;
                o[mt][nt][2] *= corr1; o[mt][nt][3] *= corr1;
            }
        }

        // ---- O += P V  (single fp16 MMA per tile: P_hi x V_hi) ----
#pragma unroll
        for (int ks = 0; ks < 4; ks++) {
            uint32_t aH[2][4];
#pragma unroll
            for (int mt = 0; mt < 2; mt++) {
#pragma unroll
                for (int half = 0; half < 2; half++) {
                    int nt = 2 * ks + half;
                    aH[mt][2 * half + 0] = pack_h2(s[mt][nt][0], s[mt][nt][1]);
                    aH[mt][2 * half + 1] = pack_h2(s[mt][nt][2], s[mt][nt][3]);
                }
            }
#pragma unroll
            for (int ntp = 0; ntp < 4; ntp++) {
                uint32_t br = st + 2 * MATB
                    + (uint32_t)((ks * 16 + (lane & 7) + ((lane >> 3) & 1) * 8) * ROWB)
                    + (uint32_t)((ntp * 16 + ((lane >> 4) & 1) * 8) * 2);
                uint32_t vh[4];
                ldsm_x4_t(vh, br);
#pragma unroll
                for (int mt = 0; mt < 2; mt++) {
                    mma16816(o[mt][2 * ntp],     aH[mt], &vh[0]);
                    mma16816(o[mt][2 * ntp + 1], aH[mt], &vh[2]);
                }
            }
        }
        __syncthreads();
    }

    // ---- epilogue: normalize, query mask, residual, fp32 store ----
#pragma unroll
    for (int mt = 0; mt < 2; mt++) {
        float qm0 = g_qmask[b * Ln + rowq[mt][0]];
        float qm1 = g_qmask[b * Ln + rowq[mt][1]];
        float f0 = qm0 / lsum[mt][0], f1 = qm1 / lsum[mt][1];
        size_t base0 = ((size_t)(b * Ln + rowq[mt][0])) * Dn + h * 64;
        size_t base1 = ((size_t)(b * Ln + rowq[mt][1])) * Dn + h * 64;
#pragma unroll
        for (int nt = 0; nt < 8; nt++) {
            int d = nt * 8 + c2;
            float2 r0v = *(const float2*)(queries + base0 + d);
            float2 r1v = *(const float2*)(queries + base1 + d);
            float2 o0, o1;
            o0.x = o[mt][nt][0] * f0 + r0v.x; o0.y = o[mt][nt][1] * f0 + r0v.y;
            o1.x = o[mt][nt][2] * f1 + r1v.x; o1.y = o[mt][nt][3] * f1 + r1v.y;
            *(float2*)(out + base0 + d) = o0;
            *(float2*)(out + base1 + d) = o1;
        }
    }
}

// ---------------------------------------------------------------------------
extern "C" void kernel_launch(void* const* d_in, const int* in_sizes, int n_in,
                              void* d_out, int out_size) {
    (void)in_sizes; (void)n_in; (void)out_size;
    const float* queries = (const float*)d_in[0];
    const float* keys    = (const float*)d_in[1];
    const float* Wq = (const float*)d_in[2];
    const float* bq = (const float*)d_in[3];
    const float* Wk = (const float*)d_in[4];
    const float* bk = (const float*)d_in[5];
    const float* Wv = (const float*)d_in[6];
    const float* bv = (const float*)d_in[7];
    float* out = (float*)d_out;

    cudaFuncSetAttribute(gemm_mma,
                         cudaFuncAttributeMaxDynamicSharedMemorySize, GEMM_SMEM);
    cudaFuncSetAttribute(attn_mma,
                         cudaFuncAttributeMaxDynamicSharedMemorySize, ATTN_SMEM);

    // 1) fused fp16 hi/lo splits + padding masks
    cvt_all<<<8384, 256>>>(queries, keys, Wq, Wk, Wv);

    // 2) QKV projections (tensor cores), fp16 hi/lo head-major outputs
    gemm_mma<<<dim3(4, 128, 3), 256, GEMM_SMEM>>>(bq, bk, bv);

    // 3) tensor-core attention + residual (PV single-MMA fp16)
    attn_mma<<<dim3(8, 8, 32), 128, ATTN_SMEM>>>(queries, out);
}

// round 11
// speedup vs baseline: 1.1655x; 1.0415x over previous
#include <cuda_runtime.h>
#include <cuda_fp16.h>
#include <math.h>
#include <cstdint>

// Problem dims (fixed by reference)
#define Bn  32
#define Ln  1024
#define Dn  512
#define Hn  8
#define DHn 64

#define NEGC (-4294967295.0f)   // -2^32 + 1, matches reference padding value
#define LOG2E 1.4426950408889634f

// ---------------------------------------------------------------------------
// Scratch (allocation-free rule: static __device__ globals)
// ---------------------------------------------------------------------------
__device__ float g_kmask[Bn * Ln];
__device__ float g_qmask[Bn * Ln];

#define NELEM_A ((size_t)Bn * Ln * Dn)      // 16,777,216
#define NELEM_W ((size_t)Dn * Dn)           // 262,144
__device__ __half g_qhi[NELEM_A];
__device__ __half g_qlo[NELEM_A];
__device__ __half g_khi[NELEM_A];
__device__ __half g_klo[NELEM_A];
__device__ __half g_whi[3][NELEM_W];
__device__ __half g_wlo[3][NELEM_W];

// Projected Q/K/V, fp16 hi/lo, head-major layout [b][h][l][64].
// z: 0 = Q (pre-scaled by log2e/8 for base-2 softmax), 1 = K, 2 = V (hi only)
__device__ __half g_prjh[3][NELEM_A];
__device__ __half g_prjl[3][NELEM_A];

// ---------------------------------------------------------------------------
// PTX helpers (sm_80-baseline only — tcgen05 does NOT assemble at .target
// sm_103 in this harness)
// ---------------------------------------------------------------------------
__device__ __forceinline__ uint32_t smem_u32(const void* p) {
    uint32_t a;
    asm("{ .reg .u64 t; cvta.to.shared.u64 t, %1; cvt.u32.u64 %0, t; }"
        : "=r"(a) : "l"(p));
    return a;
}
__device__ __forceinline__ void cp16(uint32_t dst, const void* src) {
    asm volatile("cp.async.cg.shared.global [%0], [%1], 16;\n"
                 :: "r"(dst), "l"(src) : "memory");
}
#define CP_COMMIT() asm volatile("cp.async.commit_group;\n" ::: "memory")

__device__ __forceinline__ void ldsm_x4(uint32_t* r, uint32_t addr) {
    asm volatile("ldmatrix.sync.aligned.m8n8.x4.shared.b16 {%0,%1,%2,%3}, [%4];"
                 : "=r"(r[0]), "=r"(r[1]), "=r"(r[2]), "=r"(r[3]) : "r"(addr));
}
__device__ __forceinline__ void ldsm_x4_t(uint32_t* r, uint32_t addr) {
    asm volatile("ldmatrix.sync.aligned.m8n8.x4.trans.shared.b16 {%0,%1,%2,%3}, [%4];"
                 : "=r"(r[0]), "=r"(r[1]), "=r"(r[2]), "=r"(r[3]) : "r"(addr));
}
__device__ __forceinline__ void mma16816(float* d, const uint32_t* a, const uint32_t* b) {
    asm volatile(
        "mma.sync.aligned.m16n8k16.row.col.f32.f16.f16.f32 "
        "{%0,%1,%2,%3}, {%4,%5,%6,%7}, {%8,%9}, {%0,%1,%2,%3};"
        : "+f"(d[0]), "+f"(d[1]), "+f"(d[2]), "+f"(d[3])
        : "r"(a[0]), "r"(a[1]), "r"(a[2]), "r"(a[3]), "r"(b[0]), "r"(b[1]));
}
__device__ __forceinline__ uint32_t pack_h2(float a, float b) {
    __half2 t = __floats2half2_rn(a, b);
    return *(uint32_t*)&t;
}

// ---------------------------------------------------------------------------
// Fused conversion + padding masks. One warp per 512-elem row.
// ---------------------------------------------------------------------------
__global__ void __launch_bounds__(256) cvt_all(const float* __restrict__ q,
                                               const float* __restrict__ k,
                                               const float* __restrict__ Wq,
                                               const float* __restrict__ Wk,
                                               const float* __restrict__ Wv) {
    int w = blockIdx.x * 8 + (threadIdx.x >> 5);
    int lane = threadIdx.x & 31;
    const float* src;
    __half *hi, *lo;
    float* maskp = nullptr;
    if (w < 65536) {
        int row = w & 32767;
        size_t off = (size_t)row * Dn;
        if (w < 32768) {
            src = q + off; hi = g_qhi + off; lo = g_qlo + off;
            maskp = g_qmask + row;
        } else {
            src = k + off; hi = g_khi + off; lo = g_klo + off;
            maskp = g_kmask + row;
        }
    } else {
        int r = w - 65536;
        int z = r >> 9, row = r & 511;
        size_t off = (size_t)row * Dn;
        src = (z == 0 ? Wq : (z == 1 ? Wk : Wv)) + off;
        hi = g_whi[z] + off; lo = g_wlo[z] + off;
    }
    float s = 0.f;
#pragma unroll
    for (int i = 0; i < 4; i++) {
        int f = lane + 32 * i;
        float4 v = ((const float4*)src)[f];
        s += (v.x + v.y) + (v.z + v.w);
        __half2 h0 = __floats2half2_rn(v.x, v.y);
        __half2 h1 = __floats2half2_rn(v.z, v.w);
        float2 f0 = __half22float2(h0);
        float2 f1 = __half22float2(h1);
        __half2 l0 = __floats2half2_rn(v.x - f0.x, v.y - f0.y);
        __half2 l1 = __floats2half2_rn(v.z - f1.x, v.w - f1.y);
        ((__half2*)hi)[2 * f + 0] = h0;
        ((__half2*)hi)[2 * f + 1] = h1;
        ((__half2*)lo)[2 * f + 0] = l0;
        ((__half2*)lo)[2 * f + 1] = l1;
    }
    if (maskp) {
#pragma unroll
        for (int o = 16; o; o >>= 1) s += __shfl_xor_sync(0xffffffffu, s, o);
        if (lane == 0) *maskp = (s != 0.0f) ? 1.0f : 0.0f;
    }
}

// ---------------------------------------------------------------------------
// fp16-split GEMM (mma.sync): proj_z = A_z @ W_z^T + bias_z -> fp16 hi/lo,
// head-major [b][h][l][64]; Q pre-scaled by log2e/8.
// z = 0 (Q), 1 (K): split-3 MMAs (logit accuracy).
// z = 2 (V): SINGLE MMA (A_hi x W_hi) — PV consumes only V_hi, so accuracy
//            beyond fp16 storage rounding is wasted. Also skips lo loads/stores.
// CTA tile 256x128, 8 warps, warp tile 64x64, K chunks of 32, 2-stage cp.async.
// ---------------------------------------------------------------------------
#define MATA   20480                 // 256 rows * 80B
#define MATW   10240                 // 128 rows * 80B
#define STAGE_B (2 * MATA + 2 * MATW)  // 61440
#define GEMM_SMEM (2 * STAGE_B)        // 122880

__device__ __forceinline__ void load_stage(uint32_t st,
                                           const __half* Ahi,
                                           const __half* Alo,
                                           const __half* Whi,
                                           const __half* Wlo,
                                           int bm, int bn, int kc, int tid,
                                           bool full) {
#pragma unroll
    for (int i = 0; i < 4; i++) {
        int idx = tid + 256 * i;            // 0..1023
        int row = idx >> 2, q4 = idx & 3;
        cp16(st + row * 80 + q4 * 16,
             Ahi + (size_t)(bm + row) * Dn + kc * 32 + q4 * 8);
    }
#pragma unroll
    for (int i = 0; i < 2; i++) {
        int idx = tid + 256 * i;            // 0..511
        int row = idx >> 2, q4 = idx & 3;
        cp16(st + 2 * MATA + row * 80 + q4 * 16,
             Whi + (size_t)(bn + row) * Dn + kc * 32 + q4 * 8);
    }
    if (full) {
#pragma unroll
        for (int i = 0; i < 4; i++) {
            int idx = tid + 256 * i;
            int row = idx >> 2, q4 = idx & 3;
            cp16(st + MATA + row * 80 + q4 * 16,
                 Alo + (size_t)(bm + row) * Dn + kc * 32 + q4 * 8);
        }
#pragma unroll
        for (int i = 0; i < 2; i++) {
            int idx = tid + 256 * i;
            int row = idx >> 2, q4 = idx & 3;
            cp16(st + 2 * MATA + MATW + row * 80 + q4 * 16,
                 Wlo + (size_t)(bn + row) * Dn + kc * 32 + q4 * 8);
        }
    }
    CP_COMMIT();
}

__global__ void __launch_bounds__(256, 1) gemm_mma(const float* __restrict__ bq,
                                                   const float* __restrict__ bk,
                                                   const float* __restrict__ bv) {
    extern __shared__ char smem_raw[];
    uint32_t sbase = smem_u32(smem_raw);
    int tid = threadIdx.x;
    int wid = tid >> 5, lane = tid & 31;
    int wm = wid & 3;                 // 4 warps over M (64 rows each)
    int wn = wid >> 2;                // 2 warps over N (64 cols each)
    int z = blockIdx.z;
    int bn = blockIdx.x * 128;
    int bm = blockIdx.y * 256;
    bool full = (z != 2);             // V: single-MMA path

    const __half* Ahi = (z == 0) ? g_qhi : g_khi;
    const __half* Alo = (z == 0) ? g_qlo : g_klo;
    const __half* Whi = g_whi[z];
    const __half* Wlo = g_wlo[z];
    const float* bias = (z == 0) ? bq : (z == 1 ? bk : bv);
    float scale = (z == 0) ? (0.125f * LOG2E) : 1.0f;
    __half* Ohi = g_prjh[z];
    __half* Olo = g_prjl[z];

    float acc[4][8][4];
#pragma unroll
    for (int mt = 0; mt < 4; mt++)
#pragma unroll
        for (int nt = 0; nt < 8; nt++)
#pragma unroll
            for (int e = 0; e < 4; e++) acc[mt][nt][e] = 0.f;

    int a_row = lane & 15;
    int a_koff = (lane >> 4) * 16;
    int g = lane >> 3;
    int b_nadd = ((g >> 1) & 1) * 8 + (lane & 7);
    int b_kadd = (g & 1) * 8;

    load_stage(sbase, Ahi, Alo, Whi, Wlo, bm, bn, 0, tid, full);

#pragma unroll 1
    for (int s = 0; s < 16; s++) {
        if (s < 15) {
            load_stage(sbase + (uint32_t)((s + 1) & 1) * STAGE_B,
                       Ahi, Alo, Whi, Wlo, bm, bn, s + 1, tid, full);
            asm volatile("cp.async.wait_group 1;\n" ::: "memory");
        } else {
            asm volatile("cp.async.wait_group 0;\n" ::: "memory");
        }
        __syncthreads();
        uint32_t st = sbase + (uint32_t)(s & 1) * STAGE_B;

#pragma unroll
        for (int ks = 0; ks < 32; ks += 16) {
            uint32_t aH[4][4], aL[4][4], bH[8][2], bL[8][2];
#pragma unroll
            for (int mt = 0; mt < 4; mt++) {
                uint32_t ar = st + (uint32_t)((wm * 64 + mt * 16 + a_row) * 80)
                            + a_koff + ks * 2;
                ldsm_x4(aH[mt], ar);
                if (full) ldsm_x4(aL[mt], ar + MATA);
            }
#pragma unroll
            for (int ntp = 0; ntp < 4; ntp++) {
                uint32_t br = st + 2 * MATA
                            + (uint32_t)((wn * 64 + ntp * 16 + b_nadd) * 80)
                            + (ks + b_kadd) * 2;
                uint32_t t0[4], t1[4];
                ldsm_x4(t0, br);
                bH[2 * ntp][0] = t0[0]; bH[2 * ntp][1] = t0[1];
                bH[2 * ntp + 1][0] = t0[2]; bH[2 * ntp + 1][1] = t0[3];
                if (full) {
                    ldsm_x4(t1, br + MATW);
                    bL[2 * ntp][0] = t1[0]; bL[2 * ntp][1] = t1[1];
                    bL[2 * ntp + 1][0] = t1[2]; bL[2 * ntp + 1][1] = t1[3];
                }
            }
#pragma unroll
            for (int mt = 0; mt < 4; mt++)
#pragma unroll
                for (int nt = 0; nt < 8; nt++) {
                    mma16816(acc[mt][nt], aH[mt], bH[nt]);
                    if (full) {
                        mma16816(acc[mt][nt], aH[mt], bL[nt]);
                        mma16816(acc[mt][nt], aL[mt], bH[nt]);
                    }
                }
        }
        __syncthreads();
    }

    // Epilogue: bias, scale, fp16 hi/lo split, head-major store
    int r = lane >> 2, c2 = (lane & 3) * 2;
#pragma unroll
    for (int mt = 0; mt < 4; mt++) {
#pragma unroll
        for (int nt = 0; nt < 8; nt++) {
            int col = bn + wn * 64 + nt * 8 + c2;
            float2 bb = *(const float2*)(bias + col);
            int hh = col >> 6, dd = col & 63;
#pragma unroll
            for (int half = 0; half < 2; half++) {
                int row = bm + wm * 64 + mt * 16 + r + half * 8;
                int bb_i = row >> 10, ll = row & 1023;
                size_t dst = ((size_t)((bb_i * Hn + hh) * Ln + ll)) * 64 + dd;
                float v0 = (acc[mt][nt][2 * half + 0] + bb.x) * scale;
                float v1 = (acc[mt][nt][2 * half + 1] + bb.y) * scale;
                __half2 h2v = __floats2half2_rn(v0, v1);
                *(__half2*)(Ohi + dst) = h2v;
                if (full) {
                    float2 hf = __half22float2(h2v);
                    __half2 l2v = __floats2half2_rn(v0 - hf.x, v1 - hf.y);
                    *(__half2*)(Olo + dst) = l2v;
                }
            }
        }
    }
}

// ---------------------------------------------------------------------------
// Tensor-core causal flash attention.
// S = QK^T: fp16 split-3 (accuracy for logits). O += PV: single fp16 MMA
// (P_hi x V_hi). CTA: 128 q-rows per (b,h); 4 warps x 32 rows; K tiles of 64
// double-buffered (Khi, Klo, Vhi); base-2 softmax; qt descending; 2 CTAs/SM.
// ---------------------------------------------------------------------------
#define ROWB 144                       // 72 fp16 per row
#define MATB (64 * ROWB)               // 9216
#define STG  (3 * MATB)                // 27648 (Khi, Klo, Vhi)
#define KMOFF (2 * STG)                // 55296: kmask staging (2 x 256B)
#define QOFF_H (KMOFF + 512)           // 55808
#define QOFF_L (QOFF_H + 128 * ROWB)   // 74240
#define ATTN_SMEM (QOFF_L + 128 * ROWB)   // 92672

__global__ void __launch_bounds__(128, 2) attn_mma(const float* __restrict__ queries,
                                                   float* __restrict__ out) {
    extern __shared__ char smraw[];
    uint32_t sb = smem_u32(smraw);
    int tid = threadIdx.x, wid = tid >> 5, lane = tid & 31;
    int qt = (int)gridDim.x - 1 - (int)blockIdx.x;   // heavy tiles first
    int h = blockIdx.y, b = blockIdx.z;
    int bh = b * Hn + h;
    int wq0 = wid * 32;

    const __half* Qh = g_prjh[0] + (size_t)bh * Ln * 64;
    const __half* Ql = g_prjl[0] + (size_t)bh * Ln * 64;
    const __half* Kh = g_prjh[1] + (size_t)bh * Ln * 64;
    const __half* Kl = g_prjl[1] + (size_t)bh * Ln * 64;
    const __half* Vh = g_prjh[2] + (size_t)bh * Ln * 64;

    // ---- Q tile into dedicated SMEM ----
#pragma unroll
    for (int i = 0; i < 8; i++) {
        int idx = tid + 128 * i;          // 0..1023
        int row = idx >> 3, ch = idx & 7;
        cp16(sb + QOFF_H + row * ROWB + ch * 16,
             Qh + (size_t)(qt * 128 + row) * 64 + ch * 8);
        cp16(sb + QOFF_L + row * ROWB + ch * 16,
             Ql + (size_t)(qt * 128 + row) * 64 + ch * 8);
    }
    CP_COMMIT();

    float o[2][8][4];
#pragma unroll
    for (int mt = 0; mt < 2; mt++)
#pragma unroll
        for (int nt = 0; nt < 8; nt++)
#pragma unroll
            for (int e = 0; e < 4; e++) o[mt][nt][e] = 0.f;
    float mrow[2][2], lsum[2][2];
#pragma unroll
    for (int mt = 0; mt < 2; mt++) {
        mrow[mt][0] = -INFINITY; mrow[mt][1] = -INFINITY;
        lsum[mt][0] = 0.f;       lsum[mt][1] = 0.f;
    }

    int ntk = 2 * qt + 2;

    auto load_kv = [&](int kt2) {
        uint32_t st = sb + (uint32_t)(kt2 & 1) * STG;
        int kg0 = kt2 * 64;
        const __half* srcs[3] = {Kh, Kl, Vh};
#pragma unroll
        for (int m = 0; m < 3; m++) {
#pragma unroll
            for (int i = 0; i < 4; i++) {
                int idx = tid + 128 * i;   // 0..511
                int row = idx >> 3, ch = idx & 7;
                cp16(st + m * MATB + row * ROWB + ch * 16,
                     srcs[m] + (size_t)(kg0 + row) * 64 + ch * 8);
            }
        }
        if (tid < 16)
            cp16(sb + KMOFF + (uint32_t)(kt2 & 1) * 256 + tid * 16,
                 g_kmask + b * Ln + kg0 + tid * 4);
        CP_COMMIT();
    };

    load_kv(0);

    int c2 = (lane & 3) * 2, rr = lane >> 2;
    int rowq[2][2];
#pragma unroll
    for (int mt = 0; mt < 2; mt++) {
        rowq[mt][0] = qt * 128 + wq0 + mt * 16 + rr;
        rowq[mt][1] = rowq[mt][0] + 8;
    }

#pragma unroll 1
    for (int kt = 0; kt < ntk; kt++) {
        if (kt + 1 < ntk) {
            load_kv(kt + 1);
            asm volatile("cp.async.wait_group 1;\n" ::: "memory");
        } else {
            asm volatile("cp.async.wait_group 0;\n" ::: "memory");
        }
        __syncthreads();
        uint32_t st = sb + (uint32_t)(kt & 1) * STG;

        // ---- S = Q K^T  (fp16 split-3; base-2 domain) ----
        float s[2][8][4];
#pragma unroll
        for (int mt = 0; mt < 2; mt++)
#pragma unroll
            for (int nt = 0; nt < 8; nt++)
#pragma unroll
                for (int e = 0; e < 4; e++) s[mt][nt][e] = 0.f;

#pragma unroll
        for (int dk = 0; dk < 4; dk++) {
            uint32_t qfh[2][4], qfl[2][4];
#pragma unroll
            for (int mt = 0; mt < 2; mt++) {
                uint32_t ar = sb + QOFF_H
                    + (uint32_t)((wq0 + mt * 16 + (lane & 15)) * ROWB)
                    + (uint32_t)((dk * 16 + (lane >> 4) * 8) * 2);
                ldsm_x4(qfh[mt], ar);
                ldsm_x4(qfl[mt], ar + (QOFF_L - QOFF_H));
            }
#pragma unroll
            for (int ntp = 0; ntp < 4; ntp++) {
                uint32_t br = st
                    + (uint32_t)((ntp * 16 + (lane & 7) + ((lane >> 4) & 1) * 8) * ROWB)
                    + (uint32_t)((dk * 16 + ((lane >> 3) & 1) * 8) * 2);
                uint32_t th[4], tl[4];
                ldsm_x4(th, br);
                ldsm_x4(tl, br + MATB);
#pragma unroll
                for (int mt = 0; mt < 2; mt++) {
                    mma16816(s[mt][2 * ntp],     qfh[mt], &th[0]);
                    mma16816(s[mt][2 * ntp],     qfh[mt], &tl[0]);
                    mma16816(s[mt][2 * ntp],     qfl[mt], &th[0]);
                    mma16816(s[mt][2 * ntp + 1], qfh[mt], &th[2]);
                    mma16816(s[mt][2 * ntp + 1], qfh[mt], &tl[2]);
                    mma16816(s[mt][2 * ntp + 1], qfl[mt], &th[2]);
                }
            }
        }

        // ---- masks ----
        const float* kmp = (const float*)(smraw + KMOFF + (kt & 1) * 256);
        int kbase = kt * 64;
#pragma unroll
        for (int nt = 0; nt < 8; nt++) {
            int col = kbase + nt * 8 + c2;
            float km0 = kmp[nt * 8 + c2];
            float km1 = kmp[nt * 8 + c2 + 1];
#pragma unroll
            for (int mt = 0; mt < 2; mt++) {
                if (km0 == 0.f || col > rowq[mt][0])     s[mt][nt][0] = NEGC;
                if (km1 == 0.f || col + 1 > rowq[mt][0]) s[mt][nt][1] = NEGC;
                if (km0 == 0.f || col > rowq[mt][1])     s[mt][nt][2] = NEGC;
                if (km1 == 0.f || col + 1 > rowq[mt][1]) s[mt][nt][3] = NEGC;
            }
        }

        // ---- online softmax (base-2) ----
#pragma unroll
        for (int mt = 0; mt < 2; mt++) {
            float mx0 = -INFINITY, mx1 = -INFINITY;
#pragma unroll
            for (int nt = 0; nt < 8; nt++) {
                mx0 = fmaxf(mx0, fmaxf(s[mt][nt][0], s[mt][nt][1]));
                mx1 = fmaxf(mx1, fmaxf(s[mt][nt][2], s[mt][nt][3]));
            }
            mx0 = fmaxf(mx0, __shfl_xor_sync(0xffffffffu, mx0, 1));
            mx0 = fmaxf(mx0, __shfl_xor_sync(0xffffffffu, mx0, 2));
            mx1 = fmaxf(mx1, __shfl_xor_sync(0xffffffffu, mx1, 1));
            mx1 = fmaxf(mx1, __shfl_xor_sync(0xffffffffu, mx1, 2));
            float mn0 = fmaxf(mrow[mt][0], mx0), mn1 = fmaxf(mrow[mt][1], mx1);
            float corr0 = exp2f(mrow[mt][0] - mn0), corr1 = exp2f(mrow[mt][1] - mn1);
            mrow[mt][0] = mn0; mrow[mt][1] = mn1;

            float ps0 = 0.f, ps1 = 0.f;
#pragma unroll
            for (int nt = 0; nt < 8; nt++) {
                s[mt][nt][0] = exp2f(s[mt][nt][0] - mn0);
                s[mt][nt][1] = exp2f(s[mt][nt][1] - mn0);
                s[mt][nt][2] = exp2f(s[mt][nt][2] - mn1);
                s[mt][nt][3] = exp2f(s[mt][nt][3] - mn1);
                ps0 += s[mt][nt][0] + s[mt][nt][1];
                ps1 += s[mt][nt][2] + s[mt][nt][3];
            }
            ps0 += __shfl_xor_sync(0xffffffffu, ps0, 1);
            ps0 += __shfl_xor_sync(0xffffffffu, ps0, 2);
            ps1 += __shfl_xor_sync(0xffffffffu, ps1, 1);
            ps1 += __shfl_xor_sync(0xffffffffu, ps1, 2);
            lsum[mt][0] = lsum[mt][0] * corr0 + ps0;
            lsum[mt][1] = lsum[mt][1] * corr1 + ps1;
#pragma unroll
            for (int nt = 0; nt < 8; nt++) {
                o[mt][nt][0] *= corr0; o[mt][nt][1] *= corr0;
                o[mt][nt][2] *= corr1; o[mt][nt][3] *= corr1;
            }
        }

        // ---- O += P V  (single fp16 MMA per tile: P_hi x V_hi) ----
#pragma unroll
        for (int ks = 0; ks < 4; ks++) {
            uint32_t aH[2][4];
#pragma unroll
            for (int mt = 0; mt < 2; mt++) {
#pragma unroll
                for (int half = 0; half < 2; half++) {
                    int nt = 2 * ks + half;
                    aH[mt][2 * half + 0] = pack_h2(s[mt][nt][0], s[mt][nt][1]);
                    aH[mt][2 * half + 1] = pack_h2(s[mt][nt][2], s[mt][nt][3]);
                }
            }
#pragma unroll
            for (int ntp = 0; ntp < 4; ntp++) {
                uint32_t br = st + 2 * MATB
                    + (uint32_t)((ks * 16 + (lane & 7) + ((lane >> 3) & 1) * 8) * ROWB)
                    + (uint32_t)((ntp * 16 + ((lane >> 4) & 1) * 8) * 2);
                uint32_t vh[4];
                ldsm_x4_t(vh, br);
#pragma unroll
                for (int mt = 0; mt < 2; mt++) {
                    mma16816(o[mt][2 * ntp],     aH[mt], &vh[0]);
                    mma16816(o[mt][2 * ntp + 1], aH[mt], &vh[2]);
                }
            }
        }
        __syncthreads();
    }

    // ---- epilogue: normalize, query mask, residual, fp32 store ----
#pragma unroll
    for (int mt = 0; mt < 2; mt++) {
        float qm0 = g_qmask[b * Ln + rowq[mt][0]];
        float qm1 = g_qmask[b * Ln + rowq[mt][1]];
        float f0 = qm0 / lsum[mt][0], f1 = qm1 / lsum[mt][1];
        size_t base0 = ((size_t)(b * Ln + rowq[mt][0])) * Dn + h * 64;
        size_t base1 = ((size_t)(b * Ln + rowq[mt][1])) * Dn + h * 64;
#pragma unroll
        for (int nt = 0; nt < 8; nt++) {
            int d = nt * 8 + c2;
            float2 r0v = *(const float2*)(queries + base0 + d);
            float2 r1v = *(const float2*)(queries + base1 + d);
            float2 o0, o1;
            o0.x = o[mt][nt][0] * f0 + r0v.x; o0.y = o[mt][nt][1] * f0 + r0v.y;
            o1.x = o[mt][nt][2] * f1 + r1v.x; o1.y = o[mt][nt][3] * f1 + r1v.y;
            *(float2*)(out + base0 + d) = o0;
            *(float2*)(out + base1 + d) = o1;
        }
    }
}

// ---------------------------------------------------------------------------
extern "C" void kernel_launch(void* const* d_in, const int* in_sizes, int n_in,
                              void* d_out, int out_size) {
    (void)in_sizes; (void)n_in; (void)out_size;
    const float* queries = (const float*)d_in[0];
    const float* keys    = (const float*)d_in[1];
    const float* Wq = (const float*)d_in[2];
    const float* bq = (const float*)d_in[3];
    const float* Wk = (const float*)d_in[4];
    const float* bk = (const float*)d_in[5];
    const float* Wv = (const float*)d_in[6];
    const float* bv = (const float*)d_in[7];
    float* out = (float*)d_out;

    cudaFuncSetAttribute(gemm_mma,
                         cudaFuncAttributeMaxDynamicSharedMemorySize, GEMM_SMEM);
    cudaFuncSetAttribute(attn_mma,
                         cudaFuncAttributeMaxDynamicSharedMemorySize, ATTN_SMEM);

    // 1) fused fp16 hi/lo splits + padding masks
    cvt_all<<<8384, 256>>>(queries, keys, Wq, Wk, Wv);

    // 2) QKV projections (tensor cores); V projection single-MMA
    gemm_mma<<<dim3(4, 128, 3), 256, GEMM_SMEM>>>(bq, bk, bv);

    // 3) tensor-core attention + residual (PV single-MMA fp16)
    attn_mma<<<dim3(8, 8, 32), 128, ATTN_SMEM>>>(queries, out);
}